// round 11
// baseline (speedup 1.0000x reference)
#include <cuda_runtime.h>
#include <cuda_bf16.h>
#include <stdint.h>
#include <math.h>

#define BB 8
#define TT 256
#define DD 1024
#define LL 12
#define FF 4096
#define VV 32000
#define MM (BB*TT)   // 2048 rows

// ======================= scratch (static device globals; no runtime alloc) =======================
__device__ __align__(256) float g_h [MM*DD];
__device__ __align__(256) float g_r [MM*DD];
__device__ __align__(256) float g_k [MM*DD];
__device__ __align__(256) float g_v [MM*DD];
__device__ __align__(256) float g_st[MM*DD];
__device__ __align__(256) float g_g1[MM*FF];
__device__ __align__(256) float g_g2[MM*FF];

__device__ __align__(256) __nv_bfloat16 g_xnh[MM*DD], g_xnl[MM*DD];
__device__ __align__(256) __nv_bfloat16 g_gh [MM*FF], g_gl [MM*FF];

__device__ __align__(256) __nv_bfloat16 g_wrh[LL*DD*DD], g_wrl[LL*DD*DD];
__device__ __align__(256) __nv_bfloat16 g_wkh[LL*DD*DD], g_wkl[LL*DD*DD];
__device__ __align__(256) __nv_bfloat16 g_wvh[LL*DD*DD], g_wvl[LL*DD*DD];
__device__ __align__(256) __nv_bfloat16 g_woh[LL*DD*DD], g_wol[LL*DD*DD];
__device__ __align__(256) __nv_bfloat16 g_w1h[LL*FF*DD], g_w1l[LL*FF*DD];
__device__ __align__(256) __nv_bfloat16 g_w2h[LL*FF*DD], g_w2l[LL*FF*DD];
__device__ __align__(256) __nv_bfloat16 g_o2h[LL*DD*FF], g_o2l[LL*DD*FF];
__device__ __align__(256) __nv_bfloat16 g_eh [VV*DD],    g_el [VV*DD];

// ======================= split helpers (hi = trunc bf16, lo = rn bf16 of remainder) ==========
__device__ __forceinline__ void split4(float4 v, uint2& hi, uint2& lo) {
    uint32_t h01 = __byte_perm(__float_as_uint(v.x), __float_as_uint(v.y), 0x7632);
    uint32_t h23 = __byte_perm(__float_as_uint(v.z), __float_as_uint(v.w), 0x7632);
    float lx = v.x - __uint_as_float(__float_as_uint(v.x) & 0xffff0000u);
    float ly = v.y - __uint_as_float(__float_as_uint(v.y) & 0xffff0000u);
    float lz = v.z - __uint_as_float(__float_as_uint(v.z) & 0xffff0000u);
    float lw = v.w - __uint_as_float(__float_as_uint(v.w) & 0xffff0000u);
    __nv_bfloat162 p01 = __floats2bfloat162_rn(lx, ly);
    __nv_bfloat162 p23 = __floats2bfloat162_rn(lz, lw);
    hi = make_uint2(h01, h23);
    lo = make_uint2(*reinterpret_cast<uint32_t*>(&p01), *reinterpret_cast<uint32_t*>(&p23));
}

__global__ void split_kernel(const float* __restrict__ src, __nv_bfloat16* __restrict__ hi,
                             __nv_bfloat16* __restrict__ lo) {
    size_t i = (size_t)blockIdx.x * blockDim.x + threadIdx.x;
    float4 v = ((const float4*)src)[i];
    uint2 h, l;
    split4(v, h, l);
    ((uint2*)hi)[i] = h;
    ((uint2*)lo)[i] = l;
}

// ======================= aux kernels =======================
__device__ __forceinline__ float block_reduce_sum_256(float val) {
    #pragma unroll
    for (int o = 16; o > 0; o >>= 1) val += __shfl_xor_sync(0xffffffffu, val, o);
    __shared__ float sh[8];
    __shared__ float s_tot;
    int w = threadIdx.x >> 5;
    if ((threadIdx.x & 31) == 0) sh[w] = val;
    __syncthreads();
    if (threadIdx.x < 8) {
        float v2 = sh[threadIdx.x];
        #pragma unroll
        for (int o = 4; o > 0; o >>= 1) v2 += __shfl_xor_sync(0xffu, v2, o);
        if (threadIdx.x == 0) s_tot = v2;
    }
    __syncthreads();
    return s_tot;
}
__device__ __forceinline__ float sigmoidf_(float x) { return 1.0f / (1.0f + expf(-x)); }

// embedding gather + RMSNorm -> f32 h (residual stream)
__global__ void embed_rms_kernel(const int* __restrict__ x, const float* __restrict__ embed,
                                 const float* __restrict__ w, float* __restrict__ out) {
    int row = blockIdx.x;
    int tok = x[row];
    int t = threadIdx.x;
    float4 v = ((const float4*)(embed + (size_t)tok * DD))[t];
    float ss = v.x*v.x + v.y*v.y + v.z*v.z + v.w*v.w;
    float tot = block_reduce_sum_256(ss);
    float s = rsqrtf(tot / (float)DD + 1e-6f);
    float4 wv = ((const float4*)w)[t];
    float4 o = make_float4(v.x*s*wv.x, v.y*s*wv.y, v.z*s*wv.z, v.w*s*wv.w);
    ((float4*)(out + (size_t)row * DD))[t] = o;
}

// RMSNorm (optional elementwise gate) -> bf16 hi/lo planes (feeds GEMM A)
__global__ void rms_kernel(const float* __restrict__ x, const float* __restrict__ gate,
                           const float* __restrict__ w,
                           __nv_bfloat16* __restrict__ oh, __nv_bfloat16* __restrict__ ol) {
    int row = blockIdx.x;
    int t = threadIdx.x;
    float4 v = ((const float4*)(x + (size_t)row * DD))[t];
    if (gate != nullptr) {
        float4 g = ((const float4*)(gate + (size_t)row * DD))[t];
        v.x *= g.x; v.y *= g.y; v.z *= g.z; v.w *= g.w;
    }
    float ss = v.x*v.x + v.y*v.y + v.z*v.z + v.w*v.w;
    float tot = block_reduce_sum_256(ss);
    float s = rsqrtf(tot / (float)DD + 1e-6f);
    float4 wv = ((const float4*)w)[t];
    float4 o = make_float4(v.x*s*wv.x, v.y*s*wv.y, v.z*s*wv.z, v.w*s*wv.w);
    uint2 h, l;
    split4(o, h, l);
    ((uint2*)(oh + (size_t)row * DD))[t] = h;
    ((uint2*)(ol + (size_t)row * DD))[t] = l;
}

// TimeMix decay recurrence (exact clamped-cumsum replication)
__global__ void timemix_kernel(const float* __restrict__ k, const float* __restrict__ v,
                               const float* __restrict__ decay, float* __restrict__ state) {
    int c = blockIdx.x * blockDim.x + threadIdx.x;   // [0, BB*DD)
    int b = c / DD;
    int e = c - b * DD;
    float dec = sigmoidf_(decay[e]);
    float ln  = logf(fmaxf(dec, 1e-7f));
    size_t base = (size_t)b * TT * DD + e;
    float cum = 0.0f;
    #pragma unroll 4
    for (int t = 0; t < TT; ++t) {
        float kv = k[base + (size_t)t * DD] * v[base + (size_t)t * DD];
        float sc = expf((float)t * ln);
        cum += kv / fmaxf(sc, 1e-10f);
        state[base + (size_t)t * DD] = cum * sc;
    }
}

// gated SiLU: g = silu(g1) * g2 -> bf16 hi/lo planes (feeds GEMM A)
__global__ void gate_kernel(const float* __restrict__ g1, const float* __restrict__ g2,
                            __nv_bfloat16* __restrict__ oh, __nv_bfloat16* __restrict__ ol) {
    size_t i = (size_t)blockIdx.x * blockDim.x + threadIdx.x;
    float4 a = ((const float4*)g1)[i];
    float4 b = ((const float4*)g2)[i];
    a.x = a.x * sigmoidf_(a.x) * b.x;
    a.y = a.y * sigmoidf_(a.y) * b.y;
    a.z = a.z * sigmoidf_(a.z) * b.z;
    a.w = a.w * sigmoidf_(a.w) * b.w;
    uint2 h, l;
    split4(a, h, l);
    ((uint2*)oh)[i] = h;
    ((uint2*)ol)[i] = l;
}

// ======================= common GEMM macros =======================
#define SWZ(x) ((x) ^ (((x) >> 3) & 0x70))

#define LDSM4(r, addr) \
    asm volatile("ldmatrix.sync.aligned.m8n8.x4.shared.b16 {%0,%1,%2,%3}, [%4];" \
        : "=r"((r)[0]), "=r"((r)[1]), "=r"((r)[2]), "=r"((r)[3]) : "r"(addr))

#define MMA16816(d, a, b0, b1) \
    asm volatile("mma.sync.aligned.m16n8k16.row.col.f32.bf16.bf16.f32 " \
        "{%0,%1,%2,%3}, {%4,%5,%6,%7}, {%8,%9}, {%0,%1,%2,%3};" \
        : "+f"((d)[0]), "+f"((d)[1]), "+f"((d)[2]), "+f"((d)[3]) \
        : "r"((a)[0]), "r"((a)[1]), "r"((a)[2]), "r"((a)[3]), "r"(b0), "r"(b1))

#define CP_ASYNC16(dst, src) \
    asm volatile("{ .reg .u64 g; cvta.to.global.u64 g, %1; cp.async.cg.shared.global [%0], [g], 16; }" \
        :: "r"(dst), "l"(src) : "memory")
#define CP_COMMIT() asm volatile("cp.async.commit_group;" ::: "memory")
#define CP_WAIT2()  asm volatile("cp.async.wait_group 2;" ::: "memory")
#define CP_WAIT1()  asm volatile("cp.async.wait_group 1;" ::: "memory")
#define CP_WAIT0()  asm volatile("cp.async.wait_group 0;" ::: "memory")

__device__ __forceinline__ uint32_t smem_u32(const void* p) {
    uint32_t a;
    asm("{ .reg .u64 t; cvta.to.shared.u64 t, %1; cvt.u32.u64 %0, t; }" : "=r"(a) : "l"(p));
    return a;
}

__device__ __forceinline__ float2 epi_apply2(float2 v, const float* p, int epi) {
    if (epi == 1) {
        v.x = sigmoidf_(v.x); v.y = sigmoidf_(v.y);
    } else if (epi == 2) {
        float2 c = *(const float2*)p;
        v.x += c.x; v.y += c.y;
    }
    return v;
}

// ======================= GEMM A: CTA 128x128, 1024 thr, 32 warps (4M x 8N), warp 32x16 ======
// Single-barrier 3-stage pipeline. Verified fragment layout:
// LDSM4 -> {n0k0, n0k1, n1k0, n1k1}; B pair for n-sub s = (r[2s], r[2s+1]).
#define PLANE 16384
#define STAGE128 65536   // 4 planes x 128 rows x 128B
#define NST128 3

__global__ void __launch_bounds__(1024)
gemm_hmma(const __nv_bfloat16* __restrict__ Ah, const __nv_bfloat16* __restrict__ Al,
          const __nv_bfloat16* __restrict__ Bh, const __nv_bfloat16* __restrict__ Bl,
          float* __restrict__ C, int N, int K, int epi) {
    extern __shared__ __align__(1024) char smem[];
    const uint32_t sb = smem_u32(smem);
    const int tid  = threadIdx.x;
    const int lane = tid & 31, wid = tid >> 5;
    const int wm = wid & 3;          // m offset wm*32
    const int wn = wid >> 2;         // 0..7 -> n offset wn*16
    const int bm = blockIdx.y * 128, bn = blockIdx.x * 128;

    // cp.async: 8 threads per 128B row per plane; 1x16B each
    const int lr = tid >> 3;
    const int lq = tid & 7;
    const __nv_bfloat16* psrc[4] = {
        Ah + (size_t)(bm + lr) * K + lq * 8,
        Al + (size_t)(bm + lr) * K + lq * 8,
        Bh + (size_t)(bn + lr) * K + lq * 8,
        Bl + (size_t)(bn + lr) * K + lq * 8
    };
    const uint32_t dsw = SWZ((uint32_t)(lr * 128 + lq * 16));

    const uint32_t aoff0 = (uint32_t)(wm * 32 + (lane & 15)) * 128 + (lane >> 4) * 16;
    const uint32_t boff0 = (uint32_t)(wn * 16 + ((lane >> 4) & 1) * 8 + (lane & 7)) * 128
                         + ((lane >> 3) & 1) * 16;

    float acc[2][2][4];
    #pragma unroll
    for (int mt = 0; mt < 2; ++mt)
        #pragma unroll
        for (int nt = 0; nt < 2; ++nt)
            #pragma unroll
            for (int q = 0; q < 4; ++q) acc[mt][nt][q] = 0.0f;

    const int nch = K >> 6;

    // prologue: chunks 0,1,2 into stages 0,1,2
    #pragma unroll
    for (int s = 0; s < 3; ++s) {
        const uint32_t st = sb + s * STAGE128;
        const int koff = s * 64;
        #pragma unroll
        for (int p = 0; p < 4; ++p)
            CP_ASYNC16(st + p * PLANE + dsw, psrc[p] + koff);
        CP_COMMIT();
    }
    CP_WAIT2();        // chunk 0 arrived
    __syncthreads();

    int buf = 0;
    for (int ch = 0; ch < nch; ++ch) {
        const uint32_t st = sb + buf * STAGE128;
        #pragma unroll
        for (int kk = 0; kk < 4; ++kk) {
            uint32_t ah[2][4], al[2][4], bh[4], bl[4];
            #pragma unroll
            for (int mt = 0; mt < 2; ++mt) {
                uint32_t o = SWZ(aoff0 + mt * 2048 + kk * 32);
                LDSM4(ah[mt], st + o);
                LDSM4(al[mt], st + PLANE + o);
            }
            {
                uint32_t o = SWZ(boff0 + kk * 32);
                LDSM4(bh, st + 2 * PLANE + o);
                LDSM4(bl, st + 3 * PLANE + o);
            }
            #pragma unroll
            for (int mt = 0; mt < 2; ++mt)
                #pragma unroll
                for (int nt = 0; nt < 2; ++nt)
                    MMA16816(acc[mt][nt], ah[mt], bh[nt * 2], bh[nt * 2 + 1]);
            #pragma unroll
            for (int mt = 0; mt < 2; ++mt)
                #pragma unroll
                for (int nt = 0; nt < 2; ++nt)
                    MMA16816(acc[mt][nt], ah[mt], bl[nt * 2], bl[nt * 2 + 1]);
            #pragma unroll
            for (int mt = 0; mt < 2; ++mt)
                #pragma unroll
                for (int nt = 0; nt < 2; ++nt)
                    MMA16816(acc[mt][nt], al[mt], bh[nt * 2], bh[nt * 2 + 1]);
        }
        // wait for chunk ch+1 (issued >= 1 iteration ago)
        if (ch + 2 < nch)      CP_WAIT1();
        else if (ch + 1 < nch) CP_WAIT0();
        __syncthreads();   // (a) all warps done with buf; (b) chunk ch+1 visible
        if (ch + 3 < nch) {
            const int koff = (ch + 3) * 64;
            #pragma unroll
            for (int p = 0; p < 4; ++p)
                CP_ASYNC16(st + p * PLANE + dsw, psrc[p] + koff);
            CP_COMMIT();
        }
        ++buf; if (buf == NST128) buf = 0;
    }

    // epilogue
    const int g  = lane >> 2;
    const int tc = lane & 3;
    #pragma unroll
    for (int mt = 0; mt < 2; ++mt) {
        #pragma unroll
        for (int nt = 0; nt < 2; ++nt) {
            const int r0 = bm + wm * 32 + mt * 16 + g;
            const int c  = bn + wn * 16 + nt * 8 + tc * 2;
            float* p0 = C + (size_t)r0 * N + c;
            float* p1 = C + (size_t)(r0 + 8) * N + c;
            float2 v0 = epi_apply2(make_float2(acc[mt][nt][0], acc[mt][nt][1]), p0, epi);
            float2 v1 = epi_apply2(make_float2(acc[mt][nt][2], acc[mt][nt][3]), p1, epi);
            *(float2*)p0 = v0;
            *(float2*)p1 = v1;
        }
    }
}

// ======================= GEMM B: CTA 128x256, 512 thr, 16 warps (4M x 4N), warp 32x64 ======
// For wide-N GEMMs (W1/W2/head). 2-stage single-barrier pipeline.
// B loaded per n-pair (np) to bound register pressure.
#define A_PL 16384
#define B_PL 32768
#define STAGE256 98304   // 2*A_PL + 2*B_PL
#define BH_OFF (2*A_PL)
#define BL_OFF (2*A_PL + B_PL)

__global__ void __launch_bounds__(512)
gemm_hmma_w(const __nv_bfloat16* __restrict__ Ah, const __nv_bfloat16* __restrict__ Al,
            const __nv_bfloat16* __restrict__ Bh, const __nv_bfloat16* __restrict__ Bl,
            float* __restrict__ C, int N, int K, int epi) {
    extern __shared__ __align__(1024) char smem[];
    const uint32_t sb = smem_u32(smem);
    const int tid  = threadIdx.x;
    const int lane = tid & 31, wid = tid >> 5;
    const int wm = wid & 3;          // m offset wm*32
    const int wn = wid >> 2;         // 0..3 -> n offset wn*64
    const int bm = blockIdx.y * 128, bn = blockIdx.x * 256;

    // cp.async A: 4 threads per 128B row; 2x16B each
    const int lr = tid >> 2;
    const int lq = (tid & 3) * 2;
    const __nv_bfloat16* asrcH = Ah + (size_t)(bm + lr) * K + lq * 8;
    const __nv_bfloat16* asrcL = Al + (size_t)(bm + lr) * K + lq * 8;
    uint32_t adsw[2];
    #pragma unroll
    for (int j = 0; j < 2; ++j) adsw[j] = SWZ((uint32_t)(lr * 128 + (lq + j) * 16));

    // cp.async B: 2 threads per 128B row (256 rows); 4x16B each
    const int lrB = tid >> 1;
    const int lqB = (tid & 1) * 4;
    const __nv_bfloat16* bsrcH = Bh + (size_t)(bn + lrB) * K + lqB * 8;
    const __nv_bfloat16* bsrcL = Bl + (size_t)(bn + lrB) * K + lqB * 8;
    uint32_t bdsw[4];
    #pragma unroll
    for (int j = 0; j < 4; ++j) bdsw[j] = SWZ((uint32_t)(lrB * 128 + (lqB + j) * 16));

    const uint32_t aoff0 = (uint32_t)(wm * 32 + (lane & 15)) * 128 + (lane >> 4) * 16;
    const uint32_t boff0 = (uint32_t)(wn * 64 + ((lane >> 4) & 1) * 8 + (lane & 7)) * 128
                         + ((lane >> 3) & 1) * 16;

    float acc[2][8][4];
    #pragma unroll
    for (int mt = 0; mt < 2; ++mt)
        #pragma unroll
        for (int nt = 0; nt < 8; ++nt)
            #pragma unroll
            for (int q = 0; q < 4; ++q) acc[mt][nt][q] = 0.0f;

    const int nch = K >> 6;

    // prologue: chunks 0,1
    #pragma unroll
    for (int s = 0; s < 2; ++s) {
        const uint32_t st = sb + s * STAGE256;
        const int koff = s * 64;
        #pragma unroll
        for (int j = 0; j < 2; ++j) {
            CP_ASYNC16(st + adsw[j],        asrcH + koff + j * 8);
            CP_ASYNC16(st + A_PL + adsw[j], asrcL + koff + j * 8);
        }
        #pragma unroll
        for (int j = 0; j < 4; ++j) {
            CP_ASYNC16(st + BH_OFF + bdsw[j], bsrcH + koff + j * 8);
            CP_ASYNC16(st + BL_OFF + bdsw[j], bsrcL + koff + j * 8);
        }
        CP_COMMIT();
    }
    CP_WAIT1();       // chunk 0 arrived
    __syncthreads();

    int buf = 0;
    for (int ch = 0; ch < nch; ++ch) {
        const uint32_t st = sb + buf * STAGE256;
        #pragma unroll
        for (int kk = 0; kk < 4; ++kk) {
            uint32_t ah[2][4], al[2][4];
            #pragma unroll
            for (int mt = 0; mt < 2; ++mt) {
                uint32_t o = SWZ(aoff0 + mt * 2048 + kk * 32);
                LDSM4(ah[mt], st + o);
                LDSM4(al[mt], st + A_PL + o);
            }
            #pragma unroll
            for (int np = 0; np < 4; ++np) {
                uint32_t bh[4], bl[4];
                uint32_t o = SWZ(boff0 + np * 2048 + kk * 32);
                LDSM4(bh, st + BH_OFF + o);
                LDSM4(bl, st + BL_OFF + o);
                #pragma unroll
                for (int s2 = 0; s2 < 2; ++s2) {
                    const int nt = np * 2 + s2;
                    #pragma unroll
                    for (int mt = 0; mt < 2; ++mt)
                        MMA16816(acc[mt][nt], ah[mt], bh[s2 * 2], bh[s2 * 2 + 1]);
                    #pragma unroll
                    for (int mt = 0; mt < 2; ++mt)
                        MMA16816(acc[mt][nt], ah[mt], bl[s2 * 2], bl[s2 * 2 + 1]);
                    #pragma unroll
                    for (int mt = 0; mt < 2; ++mt)
                        MMA16816(acc[mt][nt], al[mt], bh[s2 * 2], bh[s2 * 2 + 1]);
                }
            }
        }
        if (ch + 1 < nch) CP_WAIT0();
        __syncthreads();
        if (ch + 2 < nch) {
            const int koff = (ch + 2) * 64;
            #pragma unroll
            for (int j = 0; j < 2; ++j) {
                CP_ASYNC16(st + adsw[j],        asrcH + koff + j * 8);
                CP_ASYNC16(st + A_PL + adsw[j], asrcL + koff + j * 8);
            }
            #pragma unroll
            for (int j = 0; j < 4; ++j) {
                CP_ASYNC16(st + BH_OFF + bdsw[j], bsrcH + koff + j * 8);
                CP_ASYNC16(st + BL_OFF + bdsw[j], bsrcL + koff + j * 8);
            }
            CP_COMMIT();
        }
        buf ^= 1;
    }

    // epilogue
    const int g  = lane >> 2;
    const int tc = lane & 3;
    #pragma unroll
    for (int mt = 0; mt < 2; ++mt) {
        #pragma unroll
        for (int nt = 0; nt < 8; ++nt) {
            const int r0 = bm + wm * 32 + mt * 16 + g;
            const int c  = bn + wn * 64 + nt * 8 + tc * 2;
            float* p0 = C + (size_t)r0 * N + c;
            float* p1 = C + (size_t)(r0 + 8) * N + c;
            float2 v0 = epi_apply2(make_float2(acc[mt][nt][0], acc[mt][nt][1]), p0, epi);
            float2 v1 = epi_apply2(make_float2(acc[mt][nt][2], acc[mt][nt][3]), p1, epi);
            *(float2*)p0 = v0;
            *(float2*)p1 = v1;
        }
    }
}

// ======================= launch =======================
extern "C" void kernel_launch(void* const* d_in, const int* in_sizes, int n_in,
                              void* d_out, int out_size) {
    const int*   x      = (const int*)  d_in[0];
    const float* embed  = (const float*)d_in[1];
    const float* ln_in  = (const float*)d_in[2];
    const float* ln_out = (const float*)d_in[3];
    const float* ln1    = (const float*)d_in[4];
    const float* Wr     = (const float*)d_in[5];
    const float* Wk     = (const float*)d_in[6];
    const float* Wv     = (const float*)d_in[7];
    const float* Wo     = (const float*)d_in[8];
    const float* decay  = (const float*)d_in[9];
    const float* lnx    = (const float*)d_in[10];
    const float* ln2    = (const float*)d_in[11];
    const float* W1     = (const float*)d_in[12];
    const float* W2     = (const float*)d_in[13];
    const float* Wo2    = (const float*)d_in[14];
    float* out = (float*)d_out;

    float *h, *r, *k, *v, *st, *g1, *g2;
    __nv_bfloat16 *xnh, *xnl, *gh, *gl;
    __nv_bfloat16 *wrh, *wrl, *wkh, *wkl, *wvh, *wvl, *woh, *wol;
    __nv_bfloat16 *w1h, *w1l, *w2h, *w2l, *o2h, *o2l, *eh, *el;
    cudaGetSymbolAddress((void**)&h,  g_h);   cudaGetSymbolAddress((void**)&r,  g_r);
    cudaGetSymbolAddress((void**)&k,  g_k);   cudaGetSymbolAddress((void**)&v,  g_v);
    cudaGetSymbolAddress((void**)&st, g_st);  cudaGetSymbolAddress((void**)&g1, g_g1);
    cudaGetSymbolAddress((void**)&g2, g_g2);
    cudaGetSymbolAddress((void**)&xnh, g_xnh); cudaGetSymbolAddress((void**)&xnl, g_xnl);
    cudaGetSymbolAddress((void**)&gh,  g_gh);  cudaGetSymbolAddress((void**)&gl,  g_gl);
    cudaGetSymbolAddress((void**)&wrh, g_wrh); cudaGetSymbolAddress((void**)&wrl, g_wrl);
    cudaGetSymbolAddress((void**)&wkh, g_wkh); cudaGetSymbolAddress((void**)&wkl, g_wkl);
    cudaGetSymbolAddress((void**)&wvh, g_wvh); cudaGetSymbolAddress((void**)&wvl, g_wvl);
    cudaGetSymbolAddress((void**)&woh, g_woh); cudaGetSymbolAddress((void**)&wol, g_wol);
    cudaGetSymbolAddress((void**)&w1h, g_w1h); cudaGetSymbolAddress((void**)&w1l, g_w1l);
    cudaGetSymbolAddress((void**)&w2h, g_w2h); cudaGetSymbolAddress((void**)&w2l, g_w2l);
    cudaGetSymbolAddress((void**)&o2h, g_o2h); cudaGetSymbolAddress((void**)&o2l, g_o2l);
    cudaGetSymbolAddress((void**)&eh,  g_eh);  cudaGetSymbolAddress((void**)&el,  g_el);

    const int SMEM128 = NST128 * STAGE128;   // 196608
    const int SMEM256 = 2 * STAGE256;        // 196608
    cudaFuncSetAttribute(gemm_hmma,   cudaFuncAttributeMaxDynamicSharedMemorySize, SMEM128);
    cudaFuncSetAttribute(gemm_hmma_w, cudaFuncAttributeMaxDynamicSharedMemorySize, SMEM256);

    const dim3 blk(256);
    const dim3 gblk(1024);
    const dim3 wblk(512);
    const dim3 gD(DD / 128, MM / 128);     // 8 x 16    (D-GEMMs, o2)
    const dim3 gF(FF / 256, MM / 128);     // 16 x 16   (W1/W2, wide kernel)
    const dim3 gH(VV / 256, MM / 128);     // 125 x 16  (head, wide kernel)

    // ---- launch order: my index 3 = D-GEMM (profiled) ----
    split_kernel<<<(LL*DD*DD)/1024, blk>>>(Wr,  wrh, wrl);                  // #0
    embed_rms_kernel<<<MM, blk>>>(x, embed, ln_in, h);                      // #1
    rms_kernel<<<MM, blk>>>(h, nullptr, ln1, xnh, xnl);                     // #2
    gemm_hmma<<<gD, gblk, SMEM128>>>(xnh, xnl, wrh, wrl, r, DD, DD, 1);     // #3 <-- profiled

    // remaining splits
    split_kernel<<<(LL*DD*DD)/1024, blk>>>(Wk,  wkh, wkl);
    split_kernel<<<(LL*DD*DD)/1024, blk>>>(Wv,  wvh, wvl);
    split_kernel<<<(LL*DD*DD)/1024, blk>>>(Wo,  woh, wol);
    split_kernel<<<(LL*FF*DD)/1024, blk>>>(W1,  w1h, w1l);
    split_kernel<<<(LL*FF*DD)/1024, blk>>>(W2,  w2h, w2l);
    split_kernel<<<(LL*DD*FF)/1024, blk>>>(Wo2, o2h, o2l);
    split_kernel<<<(VV*DD)/1024,    blk>>>(embed, eh, el);

    // finish layer 0
    gemm_hmma<<<gD, gblk, SMEM128>>>(xnh, xnl, wkh, wkl, k, DD, DD, 0);
    gemm_hmma<<<gD, gblk, SMEM128>>>(xnh, xnl, wvh, wvl, v, DD, DD, 0);
    timemix_kernel<<<(BB * DD) / 256, blk>>>(k, v, decay, st);
    rms_kernel<<<MM, blk>>>(st, r, lnx, xnh, xnl);
    gemm_hmma<<<gD, gblk, SMEM128>>>(xnh, xnl, woh, wol, h, DD, DD, 2);
    rms_kernel<<<MM, blk>>>(h, nullptr, ln2, xnh, xnl);
    gemm_hmma_w<<<gF, wblk, SMEM256>>>(xnh, xnl, w1h, w1l, g1, FF, DD, 0);
    gemm_hmma_w<<<gF, wblk, SMEM256>>>(xnh, xnl, w2h, w2l, g2, FF, DD, 0);
    gate_kernel<<<(MM * FF / 4) / 256, blk>>>(g1, g2, gh, gl);
    gemm_hmma<<<gD, gblk, SMEM128>>>(gh, gl, o2h, o2l, h, DD, FF, 2);

    for (int l = 1; l < LL; ++l) {
        const size_t oDD = (size_t)l * DD * DD;
        const size_t oFD = (size_t)l * FF * DD;

        // --- TimeMix ---
        rms_kernel<<<MM, blk>>>(h, nullptr, ln1 + l * DD, xnh, xnl);
        gemm_hmma<<<gD, gblk, SMEM128>>>(xnh, xnl, wrh + oDD, wrl + oDD, r, DD, DD, 1);
        gemm_hmma<<<gD, gblk, SMEM128>>>(xnh, xnl, wkh + oDD, wkl + oDD, k, DD, DD, 0);
        gemm_hmma<<<gD, gblk, SMEM128>>>(xnh, xnl, wvh + oDD, wvl + oDD, v, DD, DD, 0);
        timemix_kernel<<<(BB * DD) / 256, blk>>>(k, v, decay + l * DD, st);
        rms_kernel<<<MM, blk>>>(st, r, lnx + l * DD, xnh, xnl);
        gemm_hmma<<<gD, gblk, SMEM128>>>(xnh, xnl, woh + oDD, wol + oDD, h, DD, DD, 2);

        // --- ChannelMix ---
        rms_kernel<<<MM, blk>>>(h, nullptr, ln2 + l * DD, xnh, xnl);
        gemm_hmma_w<<<gF, wblk, SMEM256>>>(xnh, xnl, w1h + oFD, w1l + oFD, g1, FF, DD, 0);
        gemm_hmma_w<<<gF, wblk, SMEM256>>>(xnh, xnl, w2h + oFD, w2l + oFD, g2, FF, DD, 0);
        gate_kernel<<<(MM * FF / 4) / 256, blk>>>(g1, g2, gh, gl);
        gemm_hmma<<<gD, gblk, SMEM128>>>(gh, gl, o2h + oFD, o2l + oFD, h, DD, FF, 2);
    }

    // --- tied head ---
    rms_kernel<<<MM, blk>>>(h, nullptr, ln_out, xnh, xnl);
    gemm_hmma_w<<<gH, wblk, SMEM256>>>(xnh, xnl, eh, el, out, VV, DD, 0);
}

// round 12
// speedup vs baseline: 1.0432x; 1.0432x over previous
#include <cuda_runtime.h>
#include <cuda_bf16.h>
#include <stdint.h>
#include <math.h>

#define BB 8
#define TT 256
#define DD 1024
#define LL 12
#define FF 4096
#define VV 32000
#define MM (BB*TT)   // 2048 rows

// ======================= scratch (static device globals; no runtime alloc) =======================
__device__ __align__(256) float g_h [MM*DD];
__device__ __align__(256) float g_r [MM*DD];
__device__ __align__(256) float g_k [MM*DD];
__device__ __align__(256) float g_v [MM*DD];
__device__ __align__(256) float g_st[MM*DD];
__device__ __align__(256) float g_g1[MM*FF];
__device__ __align__(256) float g_g2[MM*FF];

__device__ __align__(256) __nv_bfloat16 g_xnh[MM*DD], g_xnl[MM*DD];
__device__ __align__(256) __nv_bfloat16 g_gh [MM*FF], g_gl [MM*FF];

__device__ __align__(256) __nv_bfloat16 g_wrh[LL*DD*DD], g_wrl[LL*DD*DD];
__device__ __align__(256) __nv_bfloat16 g_wkh[LL*DD*DD], g_wkl[LL*DD*DD];
__device__ __align__(256) __nv_bfloat16 g_wvh[LL*DD*DD], g_wvl[LL*DD*DD];
__device__ __align__(256) __nv_bfloat16 g_woh[LL*DD*DD], g_wol[LL*DD*DD];
__device__ __align__(256) __nv_bfloat16 g_w1h[LL*FF*DD], g_w1l[LL*FF*DD];
__device__ __align__(256) __nv_bfloat16 g_w2h[LL*FF*DD], g_w2l[LL*FF*DD];
__device__ __align__(256) __nv_bfloat16 g_o2h[LL*DD*FF], g_o2l[LL*DD*FF];
__device__ __align__(256) __nv_bfloat16 g_eh [VV*DD],    g_el [VV*DD];

// ======================= split helpers (hi = trunc bf16, lo = rn bf16 of remainder) ==========
__device__ __forceinline__ void split4(float4 v, uint2& hi, uint2& lo) {
    uint32_t h01 = __byte_perm(__float_as_uint(v.x), __float_as_uint(v.y), 0x7632);
    uint32_t h23 = __byte_perm(__float_as_uint(v.z), __float_as_uint(v.w), 0x7632);
    float lx = v.x - __uint_as_float(__float_as_uint(v.x) & 0xffff0000u);
    float ly = v.y - __uint_as_float(__float_as_uint(v.y) & 0xffff0000u);
    float lz = v.z - __uint_as_float(__float_as_uint(v.z) & 0xffff0000u);
    float lw = v.w - __uint_as_float(__float_as_uint(v.w) & 0xffff0000u);
    __nv_bfloat162 p01 = __floats2bfloat162_rn(lx, ly);
    __nv_bfloat162 p23 = __floats2bfloat162_rn(lz, lw);
    hi = make_uint2(h01, h23);
    lo = make_uint2(*reinterpret_cast<uint32_t*>(&p01), *reinterpret_cast<uint32_t*>(&p23));
}

__global__ void split_kernel(const float* __restrict__ src, __nv_bfloat16* __restrict__ hi,
                             __nv_bfloat16* __restrict__ lo) {
    size_t i = (size_t)blockIdx.x * blockDim.x + threadIdx.x;
    float4 v = ((const float4*)src)[i];
    uint2 h, l;
    split4(v, h, l);
    ((uint2*)hi)[i] = h;
    ((uint2*)lo)[i] = l;
}

// ======================= aux kernels =======================
__device__ __forceinline__ float block_reduce_sum_256(float val) {
    #pragma unroll
    for (int o = 16; o > 0; o >>= 1) val += __shfl_xor_sync(0xffffffffu, val, o);
    __shared__ float sh[8];
    __shared__ float s_tot;
    int w = threadIdx.x >> 5;
    if ((threadIdx.x & 31) == 0) sh[w] = val;
    __syncthreads();
    if (threadIdx.x < 8) {
        float v2 = sh[threadIdx.x];
        #pragma unroll
        for (int o = 4; o > 0; o >>= 1) v2 += __shfl_xor_sync(0xffu, v2, o);
        if (threadIdx.x == 0) s_tot = v2;
    }
    __syncthreads();
    return s_tot;
}
__device__ __forceinline__ float sigmoidf_(float x) { return 1.0f / (1.0f + expf(-x)); }

// embedding gather + RMSNorm -> f32 h (residual stream)
__global__ void embed_rms_kernel(const int* __restrict__ x, const float* __restrict__ embed,
                                 const float* __restrict__ w, float* __restrict__ out) {
    int row = blockIdx.x;
    int tok = x[row];
    int t = threadIdx.x;
    float4 v = ((const float4*)(embed + (size_t)tok * DD))[t];
    float ss = v.x*v.x + v.y*v.y + v.z*v.z + v.w*v.w;
    float tot = block_reduce_sum_256(ss);
    float s = rsqrtf(tot / (float)DD + 1e-6f);
    float4 wv = ((const float4*)w)[t];
    float4 o = make_float4(v.x*s*wv.x, v.y*s*wv.y, v.z*s*wv.z, v.w*s*wv.w);
    ((float4*)(out + (size_t)row * DD))[t] = o;
}

// RMSNorm (optional elementwise gate) -> bf16 hi/lo planes (feeds GEMM A)
__global__ void rms_kernel(const float* __restrict__ x, const float* __restrict__ gate,
                           const float* __restrict__ w,
                           __nv_bfloat16* __restrict__ oh, __nv_bfloat16* __restrict__ ol) {
    int row = blockIdx.x;
    int t = threadIdx.x;
    float4 v = ((const float4*)(x + (size_t)row * DD))[t];
    if (gate != nullptr) {
        float4 g = ((const float4*)(gate + (size_t)row * DD))[t];
        v.x *= g.x; v.y *= g.y; v.z *= g.z; v.w *= g.w;
    }
    float ss = v.x*v.x + v.y*v.y + v.z*v.z + v.w*v.w;
    float tot = block_reduce_sum_256(ss);
    float s = rsqrtf(tot / (float)DD + 1e-6f);
    float4 wv = ((const float4*)w)[t];
    float4 o = make_float4(v.x*s*wv.x, v.y*s*wv.y, v.z*s*wv.z, v.w*s*wv.w);
    uint2 h, l;
    split4(o, h, l);
    ((uint2*)(oh + (size_t)row * DD))[t] = h;
    ((uint2*)(ol + (size_t)row * DD))[t] = l;
}

// TimeMix decay recurrence (exact clamped-cumsum replication)
__global__ void timemix_kernel(const float* __restrict__ k, const float* __restrict__ v,
                               const float* __restrict__ decay, float* __restrict__ state) {
    int c = blockIdx.x * blockDim.x + threadIdx.x;   // [0, BB*DD)
    int b = c / DD;
    int e = c - b * DD;
    float dec = sigmoidf_(decay[e]);
    float ln  = logf(fmaxf(dec, 1e-7f));
    size_t base = (size_t)b * TT * DD + e;
    float cum = 0.0f;
    #pragma unroll 4
    for (int t = 0; t < TT; ++t) {
        float kv = k[base + (size_t)t * DD] * v[base + (size_t)t * DD];
        float sc = expf((float)t * ln);
        cum += kv / fmaxf(sc, 1e-10f);
        state[base + (size_t)t * DD] = cum * sc;
    }
}

// gated SiLU: g = silu(g1) * g2 -> bf16 hi/lo planes (feeds GEMM A)
__global__ void gate_kernel(const float* __restrict__ g1, const float* __restrict__ g2,
                            __nv_bfloat16* __restrict__ oh, __nv_bfloat16* __restrict__ ol) {
    size_t i = (size_t)blockIdx.x * blockDim.x + threadIdx.x;
    float4 a = ((const float4*)g1)[i];
    float4 b = ((const float4*)g2)[i];
    a.x = a.x * sigmoidf_(a.x) * b.x;
    a.y = a.y * sigmoidf_(a.y) * b.y;
    a.z = a.z * sigmoidf_(a.z) * b.z;
    a.w = a.w * sigmoidf_(a.w) * b.w;
    uint2 h, l;
    split4(a, h, l);
    ((uint2*)oh)[i] = h;
    ((uint2*)ol)[i] = l;
}

// ======================= common GEMM macros =======================
#define SWZ(x) ((x) ^ (((x) >> 3) & 0x70))

#define LDSM4(r, addr) \
    asm volatile("ldmatrix.sync.aligned.m8n8.x4.shared.b16 {%0,%1,%2,%3}, [%4];" \
        : "=r"((r)[0]), "=r"((r)[1]), "=r"((r)[2]), "=r"((r)[3]) : "r"(addr))

#define MMA16816(d, a, b0, b1) \
    asm volatile("mma.sync.aligned.m16n8k16.row.col.f32.bf16.bf16.f32 " \
        "{%0,%1,%2,%3}, {%4,%5,%6,%7}, {%8,%9}, {%0,%1,%2,%3};" \
        : "+f"((d)[0]), "+f"((d)[1]), "+f"((d)[2]), "+f"((d)[3]) \
        : "r"((a)[0]), "r"((a)[1]), "r"((a)[2]), "r"((a)[3]), "r"(b0), "r"(b1))

#define CP_ASYNC16(dst, src) \
    asm volatile("{ .reg .u64 g; cvta.to.global.u64 g, %1; cp.async.cg.shared.global [%0], [g], 16; }" \
        :: "r"(dst), "l"(src) : "memory")
#define CP_COMMIT() asm volatile("cp.async.commit_group;" ::: "memory")
#define CP_WAIT2()  asm volatile("cp.async.wait_group 2;" ::: "memory")
#define CP_WAIT1()  asm volatile("cp.async.wait_group 1;" ::: "memory")
#define CP_WAIT0()  asm volatile("cp.async.wait_group 0;" ::: "memory")

__device__ __forceinline__ uint32_t smem_u32(const void* p) {
    uint32_t a;
    asm("{ .reg .u64 t; cvta.to.shared.u64 t, %1; cvt.u32.u64 %0, t; }" : "=r"(a) : "l"(p));
    return a;
}

__device__ __forceinline__ float2 epi_apply2(float2 v, const float* p, int epi) {
    if (epi == 1) {
        v.x = sigmoidf_(v.x); v.y = sigmoidf_(v.y);
    } else if (epi == 2) {
        float2 c = *(const float2*)p;
        v.x += c.x; v.y += c.y;
    }
    return v;
}

// ======================= GEMM: CTA 128x128, 1024 thr, 32 warps (4M x 8N), warp 32x16 ======
// Single-barrier 3-stage cp.async pipeline. Verified fragment layout:
// LDSM4 -> {n0k0, n0k1, n1k0, n1k1}; B pair for n-sub s = (r[2s], r[2s+1]).
// epi: 0 = store, 1 = sigmoid, 2 = residual add.
#define PLANE 16384
#define STAGE128 65536   // 4 planes x 128 rows x 128B
#define NST128 3

__global__ void __launch_bounds__(1024)
gemm_hmma(const __nv_bfloat16* __restrict__ Ah, const __nv_bfloat16* __restrict__ Al,
          const __nv_bfloat16* __restrict__ Bh, const __nv_bfloat16* __restrict__ Bl,
          float* __restrict__ C, int N, int K, int epi) {
    extern __shared__ __align__(1024) char smem[];
    const uint32_t sb = smem_u32(smem);
    const int tid  = threadIdx.x;
    const int lane = tid & 31, wid = tid >> 5;
    const int wm = wid & 3;          // m offset wm*32
    const int wn = wid >> 2;         // 0..7 -> n offset wn*16
    const int bm = blockIdx.y * 128, bn = blockIdx.x * 128;

    // cp.async: 8 threads per 128B row per plane; 1x16B each
    const int lr = tid >> 3;
    const int lq = tid & 7;
    const __nv_bfloat16* psrc[4] = {
        Ah + (size_t)(bm + lr) * K + lq * 8,
        Al + (size_t)(bm + lr) * K + lq * 8,
        Bh + (size_t)(bn + lr) * K + lq * 8,
        Bl + (size_t)(bn + lr) * K + lq * 8
    };
    const uint32_t dsw = SWZ((uint32_t)(lr * 128 + lq * 16));

    const uint32_t aoff0 = (uint32_t)(wm * 32 + (lane & 15)) * 128 + (lane >> 4) * 16;
    const uint32_t boff0 = (uint32_t)(wn * 16 + ((lane >> 4) & 1) * 8 + (lane & 7)) * 128
                         + ((lane >> 3) & 1) * 16;

    float acc[2][2][4];
    #pragma unroll
    for (int mt = 0; mt < 2; ++mt)
        #pragma unroll
        for (int nt = 0; nt < 2; ++nt)
            #pragma unroll
            for (int q = 0; q < 4; ++q) acc[mt][nt][q] = 0.0f;

    const int nch = K >> 6;

    // prologue: chunks 0,1,2 into stages 0,1,2
    #pragma unroll
    for (int s = 0; s < 3; ++s) {
        const uint32_t st = sb + s * STAGE128;
        const int koff = s * 64;
        #pragma unroll
        for (int p = 0; p < 4; ++p)
            CP_ASYNC16(st + p * PLANE + dsw, psrc[p] + koff);
        CP_COMMIT();
    }
    CP_WAIT2();        // chunk 0 arrived
    __syncthreads();

    int buf = 0;
    for (int ch = 0; ch < nch; ++ch) {
        const uint32_t st = sb + buf * STAGE128;
        #pragma unroll
        for (int kk = 0; kk < 4; ++kk) {
            uint32_t ah[2][4], al[2][4], bh[4], bl[4];
            #pragma unroll
            for (int mt = 0; mt < 2; ++mt) {
                uint32_t o = SWZ(aoff0 + mt * 2048 + kk * 32);
                LDSM4(ah[mt], st + o);
                LDSM4(al[mt], st + PLANE + o);
            }
            {
                uint32_t o = SWZ(boff0 + kk * 32);
                LDSM4(bh, st + 2 * PLANE + o);
                LDSM4(bl, st + 3 * PLANE + o);
            }
            #pragma unroll
            for (int mt = 0; mt < 2; ++mt)
                #pragma unroll
                for (int nt = 0; nt < 2; ++nt)
                    MMA16816(acc[mt][nt], ah[mt], bh[nt * 2], bh[nt * 2 + 1]);
            #pragma unroll
            for (int mt = 0; mt < 2; ++mt)
                #pragma unroll
                for (int nt = 0; nt < 2; ++nt)
                    MMA16816(acc[mt][nt], ah[mt], bl[nt * 2], bl[nt * 2 + 1]);
            #pragma unroll
            for (int mt = 0; mt < 2; ++mt)
                #pragma unroll
                for (int nt = 0; nt < 2; ++nt)
                    MMA16816(acc[mt][nt], al[mt], bh[nt * 2], bh[nt * 2 + 1]);
        }
        // wait for chunk ch+1 (issued >= 1 iteration ago)
        if (ch + 2 < nch)      CP_WAIT1();
        else if (ch + 1 < nch) CP_WAIT0();
        __syncthreads();   // (a) all warps done with buf; (b) chunk ch+1 visible
        if (ch + 3 < nch) {
            const int koff = (ch + 3) * 64;
            #pragma unroll
            for (int p = 0; p < 4; ++p)
                CP_ASYNC16(st + p * PLANE + dsw, psrc[p] + koff);
            CP_COMMIT();
        }
        ++buf; if (buf == NST128) buf = 0;
    }

    // epilogue
    const int g  = lane >> 2;
    const int tc = lane & 3;
    #pragma unroll
    for (int mt = 0; mt < 2; ++mt) {
        #pragma unroll
        for (int nt = 0; nt < 2; ++nt) {
            const int r0 = bm + wm * 32 + mt * 16 + g;
            const int c  = bn + wn * 16 + nt * 8 + tc * 2;
            float* p0 = C + (size_t)r0 * N + c;
            float* p1 = C + (size_t)(r0 + 8) * N + c;
            float2 v0 = epi_apply2(make_float2(acc[mt][nt][0], acc[mt][nt][1]), p0, epi);
            float2 v1 = epi_apply2(make_float2(acc[mt][nt][2], acc[mt][nt][3]), p1, epi);
            *(float2*)p0 = v0;
            *(float2*)p1 = v1;
        }
    }
}

// ======================= launch =======================
extern "C" void kernel_launch(void* const* d_in, const int* in_sizes, int n_in,
                              void* d_out, int out_size) {
    const int*   x      = (const int*)  d_in[0];
    const float* embed  = (const float*)d_in[1];
    const float* ln_in  = (const float*)d_in[2];
    const float* ln_out = (const float*)d_in[3];
    const float* ln1    = (const float*)d_in[4];
    const float* Wr     = (const float*)d_in[5];
    const float* Wk     = (const float*)d_in[6];
    const float* Wv     = (const float*)d_in[7];
    const float* Wo     = (const float*)d_in[8];
    const float* decay  = (const float*)d_in[9];
    const float* lnx    = (const float*)d_in[10];
    const float* ln2    = (const float*)d_in[11];
    const float* W1     = (const float*)d_in[12];
    const float* W2     = (const float*)d_in[13];
    const float* Wo2    = (const float*)d_in[14];
    float* out = (float*)d_out;

    float *h, *r, *k, *v, *st, *g1, *g2;
    __nv_bfloat16 *xnh, *xnl, *gh, *gl;
    __nv_bfloat16 *wrh, *wrl, *wkh, *wkl, *wvh, *wvl, *woh, *wol;
    __nv_bfloat16 *w1h, *w1l, *w2h, *w2l, *o2h, *o2l, *eh, *el;
    cudaGetSymbolAddress((void**)&h,  g_h);   cudaGetSymbolAddress((void**)&r,  g_r);
    cudaGetSymbolAddress((void**)&k,  g_k);   cudaGetSymbolAddress((void**)&v,  g_v);
    cudaGetSymbolAddress((void**)&st, g_st);  cudaGetSymbolAddress((void**)&g1, g_g1);
    cudaGetSymbolAddress((void**)&g2, g_g2);
    cudaGetSymbolAddress((void**)&xnh, g_xnh); cudaGetSymbolAddress((void**)&xnl, g_xnl);
    cudaGetSymbolAddress((void**)&gh,  g_gh);  cudaGetSymbolAddress((void**)&gl,  g_gl);
    cudaGetSymbolAddress((void**)&wrh, g_wrh); cudaGetSymbolAddress((void**)&wrl, g_wrl);
    cudaGetSymbolAddress((void**)&wkh, g_wkh); cudaGetSymbolAddress((void**)&wkl, g_wkl);
    cudaGetSymbolAddress((void**)&wvh, g_wvh); cudaGetSymbolAddress((void**)&wvl, g_wvl);
    cudaGetSymbolAddress((void**)&woh, g_woh); cudaGetSymbolAddress((void**)&wol, g_wol);
    cudaGetSymbolAddress((void**)&w1h, g_w1h); cudaGetSymbolAddress((void**)&w1l, g_w1l);
    cudaGetSymbolAddress((void**)&w2h, g_w2h); cudaGetSymbolAddress((void**)&w2l, g_w2l);
    cudaGetSymbolAddress((void**)&o2h, g_o2h); cudaGetSymbolAddress((void**)&o2l, g_o2l);
    cudaGetSymbolAddress((void**)&eh,  g_eh);  cudaGetSymbolAddress((void**)&el,  g_el);

    const int SMEM = NST128 * STAGE128;   // 196608
    cudaFuncSetAttribute(gemm_hmma, cudaFuncAttributeMaxDynamicSharedMemorySize, SMEM);

    const dim3 blk(256);
    const dim3 gblk(1024);
    const dim3 gD(DD / 128, MM / 128);     // 8 x 16
    const dim3 gF(FF / 128, MM / 128);     // 32 x 16
    const dim3 gH(VV / 128, MM / 128);     // 250 x 16

    // ---- launch order: my index 3 = D-GEMM (profiled) ----
    split_kernel<<<(LL*DD*DD)/1024, blk>>>(Wr,  wrh, wrl);                  // #0
    embed_rms_kernel<<<MM, blk>>>(x, embed, ln_in, h);                      // #1
    rms_kernel<<<MM, blk>>>(h, nullptr, ln1, xnh, xnl);                     // #2
    gemm_hmma<<<gD, gblk, SMEM>>>(xnh, xnl, wrh, wrl, r, DD, DD, 1);        // #3 <-- profiled

    // remaining splits
    split_kernel<<<(LL*DD*DD)/1024, blk>>>(Wk,  wkh, wkl);
    split_kernel<<<(LL*DD*DD)/1024, blk>>>(Wv,  wvh, wvl);
    split_kernel<<<(LL*DD*DD)/1024, blk>>>(Wo,  woh, wol);
    split_kernel<<<(LL*FF*DD)/1024, blk>>>(W1,  w1h, w1l);
    split_kernel<<<(LL*FF*DD)/1024, blk>>>(W2,  w2h, w2l);
    split_kernel<<<(LL*DD*FF)/1024, blk>>>(Wo2, o2h, o2l);
    split_kernel<<<(VV*DD)/1024,    blk>>>(embed, eh, el);

    // finish layer 0
    gemm_hmma<<<gD, gblk, SMEM>>>(xnh, xnl, wkh, wkl, k, DD, DD, 0);
    gemm_hmma<<<gD, gblk, SMEM>>>(xnh, xnl, wvh, wvl, v, DD, DD, 0);
    timemix_kernel<<<(BB * DD) / 256, blk>>>(k, v, decay, st);
    rms_kernel<<<MM, blk>>>(st, r, lnx, xnh, xnl);
    gemm_hmma<<<gD, gblk, SMEM>>>(xnh, xnl, woh, wol, h, DD, DD, 2);
    rms_kernel<<<MM, blk>>>(h, nullptr, ln2, xnh, xnl);
    gemm_hmma<<<gF, gblk, SMEM>>>(xnh, xnl, w1h, w1l, g1, FF, DD, 0);
    gemm_hmma<<<gF, gblk, SMEM>>>(xnh, xnl, w2h, w2l, g2, FF, DD, 0);
    gate_kernel<<<(MM * FF / 4) / 256, blk>>>(g1, g2, gh, gl);
    gemm_hmma<<<gD, gblk, SMEM>>>(gh, gl, o2h, o2l, h, DD, FF, 2);

    for (int l = 1; l < LL; ++l) {
        const size_t oDD = (size_t)l * DD * DD;
        const size_t oFD = (size_t)l * FF * DD;

        // --- TimeMix ---
        rms_kernel<<<MM, blk>>>(h, nullptr, ln1 + l * DD, xnh, xnl);
        gemm_hmma<<<gD, gblk, SMEM>>>(xnh, xnl, wrh + oDD, wrl + oDD, r, DD, DD, 1);
        gemm_hmma<<<gD, gblk, SMEM>>>(xnh, xnl, wkh + oDD, wkl + oDD, k, DD, DD, 0);
        gemm_hmma<<<gD, gblk, SMEM>>>(xnh, xnl, wvh + oDD, wvl + oDD, v, DD, DD, 0);
        timemix_kernel<<<(BB * DD) / 256, blk>>>(k, v, decay + l * DD, st);
        rms_kernel<<<MM, blk>>>(st, r, lnx + l * DD, xnh, xnl);
        gemm_hmma<<<gD, gblk, SMEM>>>(xnh, xnl, woh + oDD, wol + oDD, h, DD, DD, 2);

        // --- ChannelMix ---
        rms_kernel<<<MM, blk>>>(h, nullptr, ln2 + l * DD, xnh, xnl);
        gemm_hmma<<<gF, gblk, SMEM>>>(xnh, xnl, w1h + oFD, w1l + oFD, g1, FF, DD, 0);
        gemm_hmma<<<gF, gblk, SMEM>>>(xnh, xnl, w2h + oFD, w2l + oFD, g2, FF, DD, 0);
        gate_kernel<<<(MM * FF / 4) / 256, blk>>>(g1, g2, gh, gl);
        gemm_hmma<<<gD, gblk, SMEM>>>(gh, gl, o2h + oFD, o2l + oFD, h, DD, FF, 2);
    }

    // --- tied head ---
    rms_kernel<<<MM, blk>>>(h, nullptr, ln_out, xnh, xnl);
    gemm_hmma<<<gH, gblk, SMEM>>>(xnh, xnl, eh, el, out, VV, DD, 0);
}